// round 8
// baseline (speedup 1.0000x reference)
#include <cuda_runtime.h>
#include <cstdint>

// Problem constants
#define T_LEN 2048
#define BATCH 32
#define HID   256
#define G3    768    // 3H (weight leading dim)
#define N2    512    // only first 2H pre-columns matter (c_pre is dead)
#define NSCAN 128    // scan blocks: each owns 2 h-cols of BOTH layers
#define NTOT  148
#define NWORK (NTOT - NSCAN)   // 20 gemm workers
#define NTILE 8192   // 1024 t-pair rows * 8 col tiles

// ---------------------------------------------------------------------------
// Device scratch
// ---------------------------------------------------------------------------
__device__ float g_X[(size_t)T_LEN * N2 * BATCH];  // x@Wih0+b0, [t][c(512)][b(32)]
__device__ float g_h0[2][HID * BATCH];             // h0(t) in slot t&1, layout [k][r]
__device__ float g_h1[2][HID * BATCH];             // h1(t) in slot t&1
__device__ unsigned g_flag[NSCAN * 8];             // monotonic progress flags
__device__ unsigned g_tcnt[T_LEN / 2];             // gemm tile counters (8/run/row)
__device__ unsigned g_run;                         // completed-run epoch

// ---------------------------------------------------------------------------
// Packed f32x2 helpers
// ---------------------------------------------------------------------------
__device__ __forceinline__ unsigned long long pack2(float v) {
    unsigned long long r;
    asm("mov.b64 %0, {%1, %1};" : "=l"(r) : "f"(v));
    return r;
}
__device__ __forceinline__ void fma2(unsigned long long& d,
                                     unsigned long long a, unsigned long long b) {
    asm("fma.rn.f32x2 %0, %1, %2, %0;" : "+l"(d) : "l"(a), "l"(b));
}
__device__ __forceinline__ unsigned long long add2(unsigned long long a,
                                                   unsigned long long b) {
    unsigned long long r;
    asm("add.rn.f32x2 %0, %1, %2;" : "=l"(r) : "l"(a), "l"(b));
    return r;
}
__device__ __forceinline__ void unpack2(unsigned long long v, float& lo, float& hi) {
    asm("mov.b64 {%0, %1}, %2;" : "=f"(lo), "=f"(hi) : "l"(v));
}

// ---------------------------------------------------------------------------
// GEMM worker: grid-strided 64x64x256 tiles of g_X = input @ Wih0[:,:512]+b0.
// ---------------------------------------------------------------------------
__device__ void gemm_worker(int wb, const float* __restrict__ A,
                            const float* __restrict__ W,
                            const float* __restrict__ bias,
                            float* smem, int Lmax)
{
    float (*As)[65] = (float(*)[65])smem;
    float (*Bs)[64] = (float(*)[64])(smem + 32 * 65);

    const int tid = threadIdx.x;
    const int tx  = tid & 15;
    const int ty  = tid >> 4;
    const int ar  = tid >> 2;
    const int ak  = (tid & 3) * 8;
    const int bk  = tid >> 3;
    const int bc  = (tid & 7) * 8;

    for (int n = wb; n < NTILE; n += NWORK) {
        const int bx = n >> 3;
        if (2 * bx >= Lmax) break;
        const int m0 = bx * 64;
        const int n0 = (n & 7) * 64;

        unsigned long long acc2[4][2];
#pragma unroll
        for (int i = 0; i < 4; i++) { acc2[i][0] = 0ull; acc2[i][1] = 0ull; }

        for (int k0 = 0; k0 < 256; k0 += 32) {
            float4 a0  = *(const float4*)&A[(size_t)(m0 + ar) * 256 + k0 + ak];
            float4 a1  = *(const float4*)&A[(size_t)(m0 + ar) * 256 + k0 + ak + 4];
            float4 b0v = *(const float4*)&W[(size_t)(k0 + bk) * G3 + n0 + bc];
            float4 b1v = *(const float4*)&W[(size_t)(k0 + bk) * G3 + n0 + bc + 4];

            As[ak + 0][ar] = a0.x; As[ak + 1][ar] = a0.y;
            As[ak + 2][ar] = a0.z; As[ak + 3][ar] = a0.w;
            As[ak + 4][ar] = a1.x; As[ak + 5][ar] = a1.y;
            As[ak + 6][ar] = a1.z; As[ak + 7][ar] = a1.w;
            *(float4*)&Bs[bk][bc]     = b0v;
            *(float4*)&Bs[bk][bc + 4] = b1v;
            __syncthreads();

#pragma unroll
            for (int kk = 0; kk < 32; kk++) {
                const ulonglong2 bq = *(const ulonglong2*)&Bs[kk][ty * 4];
#pragma unroll
                for (int ri = 0; ri < 4; ri++) {
                    const unsigned long long av = pack2(As[kk][tx * 4 + ri]);
                    fma2(acc2[ri][0], bq.x, av);
                    fma2(acc2[ri][1], bq.y, av);
                }
            }
            __syncthreads();
        }

        float accf[4][4];
#pragma unroll
        for (int ri = 0; ri < 4; ri++) {
            unpack2(acc2[ri][0], accf[ri][0], accf[ri][1]);
            unpack2(acc2[ri][1], accf[ri][2], accf[ri][3]);
        }

        const int t  = bx * 2 + (tx >> 3);
        const int bb = (tx & 7) * 4;
#pragma unroll
        for (int ci = 0; ci < 4; ci++) {
            const int c = n0 + ty * 4 + ci;
            const float bv = bias[c];
            float4 v = make_float4(accf[0][ci] + bv, accf[1][ci] + bv,
                                   accf[2][ci] + bv, accf[3][ci] + bv);
            *(float4*)&g_X[((size_t)t * N2 + c) * BATCH + bb] = v;
        }

        __threadfence();
        __syncthreads();
        if (tid == 0) {
            asm volatile("red.release.gpu.global.add.u32 [%0], %1;"
                         :: "l"(&g_tcnt[bx]), "r"(1u) : "memory");
        }
    }
}

// ---------------------------------------------------------------------------
// ONE kernel, 148 blocks (1/SM):
//   blocks 0..127 : scan; block b owns h-cols {2b,2b+1} of BOTH layers.
//     warps 0-3: layer-0 dot (K=256), warps 4-7: layer-1 dot (K=512).
//   blocks 128..147: gemm workers.
// Round i: layer-0 computes h0(i) (i<Lmax); layer-1 computes h1(i-1) (i>=1).
// Staged hs = [h1(i-2) (k 0..255) ; h0(i-1) (k 256..511)], [k][r] swizzled
// with chunk ^= (k>>3)&7 (conflict-free for both layers' k-slicings).
// ---------------------------------------------------------------------------
__global__ __launch_bounds__(256, 1) void fused_all(
    const float* __restrict__ input,
    const float* __restrict__ Whh0,
    const float* __restrict__ Whh1,
    const float* __restrict__ Wih0,
    const float* __restrict__ Wih1,
    const float* __restrict__ b0,
    const float* __restrict__ b1,
    const int*   __restrict__ length,
    float* __restrict__ out1,
    float* __restrict__ hn)
{
    extern __shared__ float smem[];
    const int bid = blockIdx.x;
    const int tid = threadIdx.x;

    int Lmax = 0;
#pragma unroll 8
    for (int r = 0; r < BATCH; r++) Lmax = max(Lmax, length[r]);

    if (bid >= NSCAN) {
        gemm_worker(bid - NSCAN, input, Wih0, b0, smem, Lmax);
        return;
    }

    float* hs    = smem;                  // [512][32] swizzled (64KB)
    float* red   = smem + N2 * BATCH;     // [2 grp][4 w][4 ci][34]
    float* out_s = red + 2 * 4 * 4 * 34;  // [32][2]
    float4* hs4  = (float4*)hs;
    const ulonglong2* hsU = (const ulonglong2*)hs;

    const int wid  = tid >> 5;
    const int lane = tid & 31;
    const int grp  = wid >> 2;          // 0 = layer-0 warps, 1 = layer-1 warps
    const int ww   = wid & 3;           // warp within group
    const int kslice = lane & 7;
    const int rgrp   = lane >> 3;       // 4 row groups x 8 rows
    const int c0   = 2 * bid;           // first owned h-col

    const int kbase = grp ? (ww * 128 + kslice * 8)
                          : (256 + ww * 64 + kslice * 8);
    const int swz = (kbase >> 3) & 7;   // constant per thread
    const int o0  = (rgrp * 2)     ^ swz;
    const int o1  = (rgrp * 2 + 1) ^ swz;

    const unsigned R     = *(volatile unsigned*)&g_run;
    const unsigned fbase = R * (unsigned)(Lmax + 1);
    const unsigned tbase = R * 8u;

    // ---- weights in registers: 4 precols x (8 | 16) k ----
    float w[4][16];
    if (grp == 0) {
#pragma unroll
        for (int kk = 0; kk < 8; kk++) {
            const int krow = kbase - 256 + kk;   // row of Whh0
#pragma unroll
            for (int ci = 0; ci < 4; ci++) {
                const int pc = (ci < 2) ? (c0 + ci) : (HID + c0 + ci - 2);
                w[ci][kk] = Whh0[(size_t)krow * G3 + pc];
            }
        }
#pragma unroll
        for (int kk = 8; kk < 16; kk++)
#pragma unroll
            for (int ci = 0; ci < 4; ci++) w[ci][kk] = 0.f;
    } else {
#pragma unroll
        for (int kk = 0; kk < 16; kk++) {
            const int kst = kbase + (kk & 7) + ((kk >> 3) << 6);  // staged k
            const float* W = (kst < 256) ? Whh1 : Wih1;
            const int krow = kst & 255;
#pragma unroll
            for (int ci = 0; ci < 4; ci++) {
                const int pc = (ci < 2) ? (c0 + ci) : (HID + c0 + ci - 2);
                w[ci][kk] = W[(size_t)krow * G3 + pc];
            }
        }
    }

    // gate-thread setup: layer gl uses threads [gl*128, gl*128+64)
    const int gl   = tid >> 7;
    const bool gate_th = ((tid & 127) < 64);
    const int gr   = tid & 31;
    const int gc   = (tid >> 5) & 1;
    const int gj   = c0 + gc;
    const int glen = length[gr];
    float gbh = 0.f, gbt = 0.f;
    if (gl == 1 && gate_th) {
        gbh = b1[gj];
        gbt = b1[HID + gj];
    }

    for (int idx = tid; idx < BATCH * 2; idx += 256) out_s[idx] = 0.f;

    float hlast = 0.f;
    int rdy_row = 0;

    for (int i = 0; i <= Lmax; i++) {
        const bool act0 = (i < Lmax);
        const bool act1 = (i >= 1);

        // ---- wait: all 128 flags >= i; gemm row (i>>1) ready ----
        if (i > 0 && tid < NSCAN) {
            const unsigned target = fbase + (unsigned)i;
            unsigned v;
            do {
                asm volatile("ld.acquire.gpu.global.u32 %0, [%1];"
                             : "=r"(v) : "l"(&g_flag[tid * 8]) : "memory");
            } while ((int)(v - target) < 0);
        }
        if (tid == 255 && act0 && (i >> 1) >= rdy_row) {
            const unsigned target = tbase + 8u;
            unsigned v;
            do {
                asm volatile("ld.acquire.gpu.global.u32 %0, [%1];"
                             : "=r"(v) : "l"(&g_tcnt[i >> 1]) : "memory");
            } while ((int)(v - target) < 0);
            rdy_row = (i >> 1) + 1;
        }
        __syncthreads();

        // ---- prefetch layer-0 x-term ----
        float xh = 0.f, xt = 0.f;
        if (gl == 0 && gate_th && act0) {
            const size_t bo = ((size_t)i * N2 + gj) * BATCH + gr;
            xh = __ldg(&g_X[bo]);
            xt = __ldg(&g_X[bo + (size_t)HID * BATCH]);
        }

        // ---- stage [h1(i-2) ; h0(i-1)] ----
        if (i >= 2) {
            const float4* s = (const float4*)g_h1[i & 1];
            for (int idx = tid; idx < 2048; idx += 256) {
                const int k = idx >> 3, c = idx & 7;
                hs4[k * 8 + (c ^ ((k >> 3) & 7))] = __ldcg(s + idx);
            }
        } else {
            const float4 z = make_float4(0.f, 0.f, 0.f, 0.f);
            for (int idx = tid; idx < 2048; idx += 256) hs4[idx] = z;
        }
        if (i >= 1) {
            const float4* s = (const float4*)g_h0[(i + 1) & 1];
            for (int idx = tid; idx < 2048; idx += 256) {
                const int k = 256 + (idx >> 3), c = idx & 7;
                hs4[k * 8 + (c ^ ((k >> 3) & 7))] = __ldcg(s + idx);
            }
        } else {
            const float4 z = make_float4(0.f, 0.f, 0.f, 0.f);
            for (int idx = tid; idx < 2048; idx += 256) {
                const int k = 256 + (idx >> 3), c = idx & 7;
                hs4[k * 8 + (c ^ ((k >> 3) & 7))] = z;
            }
        }
        __syncthreads();

        // ---- dot ----
        const bool myact = grp ? act1 : act0;
        if (myact) {
            unsigned long long acc[4][4];
#pragma unroll
            for (int ci = 0; ci < 4; ci++)
#pragma unroll
                for (int p = 0; p < 4; p++) acc[ci][p] = 0ull;

            if (grp == 0) {
#pragma unroll
                for (int kk = 0; kk < 8; kk++) {
                    const int b4 = (kbase + kk) * 8;
                    const ulonglong2 ha = *(const ulonglong2*)&hs4[b4 + o0];
                    const ulonglong2 hb = *(const ulonglong2*)&hs4[b4 + o1];
#pragma unroll
                    for (int ci = 0; ci < 4; ci++) {
                        const unsigned long long w2 = pack2(w[ci][kk]);
                        fma2(acc[ci][0], ha.x, w2);
                        fma2(acc[ci][1], ha.y, w2);
                        fma2(acc[ci][2], hb.x, w2);
                        fma2(acc[ci][3], hb.y, w2);
                    }
                }
            } else {
#pragma unroll
                for (int kk = 0; kk < 16; kk++) {
                    const int kst = kbase + (kk & 7) + ((kk >> 3) << 6);
                    const int b4 = kst * 8;
                    const ulonglong2 ha = *(const ulonglong2*)&hs4[b4 + o0];
                    const ulonglong2 hb = *(const ulonglong2*)&hs4[b4 + o1];
#pragma unroll
                    for (int ci = 0; ci < 4; ci++) {
                        const unsigned long long w2 = pack2(w[ci][kk]);
                        fma2(acc[ci][0], ha.x, w2);
                        fma2(acc[ci][1], ha.y, w2);
                        fma2(acc[ci][2], hb.x, w2);
                        fma2(acc[ci][3], hb.y, w2);
                    }
                }
            }

            // reduce over kslice (lane bits 0..2)
#pragma unroll
            for (int ci = 0; ci < 4; ci++)
#pragma unroll
                for (int p = 0; p < 4; p++) {
                    unsigned long long v = acc[ci][p];
                    v = add2(v, __shfl_xor_sync(0xffffffffu, v, 1));
                    v = add2(v, __shfl_xor_sync(0xffffffffu, v, 2));
                    v = add2(v, __shfl_xor_sync(0xffffffffu, v, 4));
                    acc[ci][p] = v;
                }
            if (kslice == 0) {
#pragma unroll
                for (int ci = 0; ci < 4; ci++)
#pragma unroll
                    for (int p = 0; p < 4; p++)
                        *(unsigned long long*)&red[((grp * 4 + ww) * 4 + ci) * 34
                                                   + rgrp * 8 + 2 * p] = acc[ci][p];
            }
        }
        __syncthreads();

        // ---- gates ----
        const bool gact = gl ? act1 : act0;
        if (gate_th && gact) {
            float sh = 0.f, st = 0.f;
#pragma unroll
            for (int wp = 0; wp < 4; wp++) {
                sh += red[((gl * 4 + wp) * 4 + gc)     * 34 + gr];
                st += red[((gl * 4 + wp) * 4 + gc + 2) * 34 + gr];
            }
            const int t = gl ? (i - 1) : i;
            const float ph = sh + (gl ? gbh : xh);
            const float pt = st + (gl ? gbt : xt);
            const int kst = gl ? gj : (256 + gj);
            const float hprev = hs[kst * 32 +
                (((gr >> 2) ^ ((kst >> 3) & 7)) << 2) + (gr & 3)];
            const float tg    = 1.f / (1.f + __expf(-pt));
            const float cgate = 1.f / (1.f + __expf(-tg));   // bug-faithful
            const float sv    = tanhf(ph) * tg + hprev * cgate;
            const float hnew  = (t < glen) ? sv : hprev;
            hlast = hnew;
            if (gl) {
                g_h1[(i - 1) & 1][gj * BATCH + gr] = hnew;
                out_s[gr * 2 + gc] = hnew;
            } else {
                g_h0[i & 1][gj * BATCH + gr] = hnew;
            }
        }
        __syncthreads();

        // ---- publish ----
        if (tid == 0) {
            asm volatile("st.release.gpu.global.u32 [%0], %1;"
                         :: "l"(&g_flag[bid * 8]), "r"(fbase + (unsigned)(i + 1))
                         : "memory");
        }

        // ---- out1 write off the critical path ----
        if (act1 && tid >= 128 && tid < 160) {
            const int r = tid - 128;
            const float2 v = *(const float2*)&out_s[r * 2];
            *(float2*)&out1[((size_t)(i - 1) * BATCH + r) * HID + c0] = v;
        }
    }

    // ---- epilogue: hn + frozen-tail fill ----
    if (gate_th) {
        if (gl) hn[BATCH * HID + gr * HID + gj] = hlast;
        else    hn[gr * HID + gj] = hlast;
    }
    __syncthreads();
    {
        const int ntail = (T_LEN - Lmax) * BATCH;
        for (int idx = tid; idx < ntail; idx += 256) {
            const int tt = Lmax + (idx >> 5), r = idx & 31;
            *(float2*)&out1[((size_t)tt * BATCH + r) * HID + c0] =
                *(const float2*)&out_s[r * 2];
        }
    }

    // ---- run-completion: block 0 advances the epoch ----
    if (bid == 0) {
        if (tid < NSCAN) {
            const unsigned target = fbase + (unsigned)(Lmax + 1);
            unsigned v;
            do {
                asm volatile("ld.acquire.gpu.global.u32 %0, [%1];"
                             : "=r"(v) : "l"(&g_flag[tid * 8]) : "memory");
            } while ((int)(v - target) < 0);
        }
        __syncthreads();
        if (tid == 0) *(volatile unsigned*)&g_run = R + 1u;
    }
}

// ---------------------------------------------------------------------------
extern "C" void kernel_launch(void* const* d_in, const int* in_sizes, int n_in,
                              void* d_out, int out_size) {
    const float* input  = (const float*)d_in[0];
    const int*   length = (const int*)d_in[1];
    const float* Wih0   = (const float*)d_in[2];
    const float* Whh0   = (const float*)d_in[3];
    const float* b0     = (const float*)d_in[4];
    const float* Wih1   = (const float*)d_in[5];
    const float* Whh1   = (const float*)d_in[6];
    const float* b1     = (const float*)d_in[7];

    float* out1 = (float*)d_out;
    float* hn   = (float*)d_out + (size_t)T_LEN * BATCH * HID;

    const int smem_bytes = (N2 * BATCH + 2 * 4 * 4 * 34 + BATCH * 2) * 4;
    static bool attr_set = false;
    if (!attr_set) {
        cudaFuncSetAttribute(fused_all, cudaFuncAttributeMaxDynamicSharedMemorySize,
                             smem_bytes);
        attr_set = true;
    }

    fused_all<<<NTOT, 256, smem_bytes>>>(
        input, Whh0, Whh1, Wih0, Wih1, b0, b1, length, out1, hn);
}